// round 1
// baseline (speedup 1.0000x reference)
#include <cuda_runtime.h>
#include <math.h>

typedef unsigned long long ull;

#define NBLK 128
#define NTHR 256
#define BB   32
#define CC   1024
#define C2   2048
#define TT   1024
#define KC   128
#define WA_STR 2050
#define WB_STR 2050
#define ACT_STR 132

// SMEM layout (floats):
//   sWa : 16*2050 = 32800
//   sWb :  8*2050 = 16400
//   sAct: 32*132  =  4224
//   sRed:            2048
#define SMEM_FLOATS (16*WA_STR + 8*WB_STR + 32*ACT_STR + 2048)
#define SMEM_BYTES  (SMEM_FLOATS * 4)

__device__ float g_h [BB*CC];
__device__ float g_y [BB*C2];
__device__ float g_y2[BB*CC];
__device__ unsigned g_cnt;
__device__ volatile unsigned g_gen;

__device__ __forceinline__ void ffma2(ull& d, ull a, ull b) {
    asm volatile("fma.rn.f32x2 %0, %1, %2, %0;" : "+l"(d) : "l"(a), "l"(b));
}
__device__ __forceinline__ ull ld64(const float* p) {
    return *reinterpret_cast<const ull*>(p);
}
__device__ __forceinline__ float hsum(ull a) {
    return __uint_as_float((unsigned)a) + __uint_as_float((unsigned)(a >> 32));
}
__device__ __forceinline__ float geluf(float u) {
    return 0.5f * u * (1.0f + erff(u * 0.70710678118654752440f));
}

// Grid-wide barrier: counter + generation. Replay-safe (cnt returns to 0,
// gen monotonic). All 128 CTAs are co-resident (1 CTA/SM via SMEM).
__device__ __forceinline__ void gbar() {
    __syncthreads();
    if (threadIdx.x == 0) {
        __threadfence();
        unsigned gen = g_gen;
        if (atomicAdd(&g_cnt, 1u) == NBLK - 1) {
            atomicExch(&g_cnt, 0u);
            __threadfence();
            g_gen = gen + 1u;
        } else {
            while (g_gen == gen) {}
        }
        __threadfence();
    }
    __syncthreads();
}

__global__ void __launch_bounds__(NTHR, 1)
rnn_kernel(const float* __restrict__ x,   const float* __restrict__ Wa,
           const float* __restrict__ ba,  const float* __restrict__ Wb,
           const float* __restrict__ bbv, const float* __restrict__ gamma,
           const float* __restrict__ beta, float* __restrict__ out)
{
    extern __shared__ float sm[];
    float* sWa  = sm;
    float* sWb  = sm + 16*WA_STR;
    float* sAct = sWb + 8*WB_STR;
    float* sRed = sAct + 32*ACT_STR;

    const int tid = threadIdx.x;
    const int cta = blockIdx.x;

    // Load this CTA's weight slices into SMEM once (reused for all 1024 steps).
    for (int idx = tid; idx < 16*C2; idx += NTHR) {
        int r = idx >> 11, k = idx & (C2-1);
        sWa[r*WA_STR + k] = Wa[(size_t)(cta*16 + r)*C2 + k];
    }
    for (int idx = tid; idx < 8*C2; idx += NTHR) {
        int r = idx >> 11, k = idx & (C2-1);
        sWb[r*WB_STR + k] = Wb[(size_t)(cta*8 + r)*C2 + k];
    }
    // h0 = 0 (exactly 128*256 = 32768 elements)
    g_h[cta*NTHR + tid] = 0.0f;
    gbar();

    // Phase A mapping: 64 slots (8 b-groups x 8 j-groups), 4-way k-split.
    const int aSlot = tid & 63, aKs = tid >> 6;
    const int aB = aSlot & 7, aJ = aSlot >> 3;
    // Phase B mapping: 32 slots (8 b-groups x 4 j-groups), 8-way k-split.
    const int bSlot = tid & 31, bKs = tid >> 5;
    const int bB = bSlot & 7, bJ = bSlot >> 3;
    // Phase C mapping: 4 CTAs per batch row.
    const int myB = cta >> 2, myQ = cta & 3;

    for (int t = 0; t < TT; ++t) {
        // ================= Phase A: y = gelu([h, x_t] @ Wa^T + ba) =================
        ull acc[4][2];
        #pragma unroll
        for (int i = 0; i < 4; ++i) { acc[i][0] = 0ull; acc[i][1] = 0ull; }

        for (int kc = 0; kc < C2; kc += KC) {
            __syncthreads();
            const float* base; size_t str;
            if (kc < CC) { base = g_h + kc;                          str = CC; }
            else         { base = x + (size_t)t*CC + (kc - CC);      str = (size_t)TT*CC; }
            for (int idx = tid; idx < BB*KC; idx += NTHR) {
                int b = idx >> 7, kk = idx & (KC-1);
                sAct[b*ACT_STR + kk] = __ldcg(base + (size_t)b*str + kk);
            }
            __syncthreads();

            const float* w0p = sWa + (2*aJ)*WA_STR + kc;
            const float* w1p = w0p + WA_STR;
            const int kb = aKs * 32;
            #pragma unroll
            for (int kk = 0; kk < 32; kk += 2) {
                ull w0 = ld64(w0p + kb + kk);
                ull w1 = ld64(w1p + kb + kk);
                #pragma unroll
                for (int i = 0; i < 4; ++i) {
                    ull a = ld64(sAct + (aB + 8*i)*ACT_STR + kb + kk);
                    ffma2(acc[i][0], a, w0);
                    ffma2(acc[i][1], a, w1);
                }
            }
        }
        {
            float part[4][2];
            #pragma unroll
            for (int i = 0; i < 4; ++i) {
                part[i][0] = hsum(acc[i][0]);
                part[i][1] = hsum(acc[i][1]);
            }
            if (aKs) {
                #pragma unroll
                for (int i = 0; i < 4; ++i) {
                    sRed[(((aKs-1)*64 + aSlot)*8) + i*2 + 0] = part[i][0];
                    sRed[(((aKs-1)*64 + aSlot)*8) + i*2 + 1] = part[i][1];
                }
            }
            __syncthreads();
            if (aKs == 0) {
                #pragma unroll
                for (int i = 0; i < 4; ++i) {
                    #pragma unroll
                    for (int j = 0; j < 2; ++j) {
                        float v = part[i][j];
                        #pragma unroll
                        for (int p = 0; p < 3; ++p)
                            v += sRed[((p*64 + aSlot)*8) + i*2 + j];
                        int jg = cta*16 + 2*aJ + j;
                        float u = v + __ldg(ba + jg);
                        __stcg(&g_y[(size_t)(aB + 8*i)*C2 + jg], geluf(u));
                    }
                }
            }
        }
        gbar();

        // ================= Phase B: y2 = y @ Wb^T + bb =================
        ull acc2[4][2];
        #pragma unroll
        for (int i = 0; i < 4; ++i) { acc2[i][0] = 0ull; acc2[i][1] = 0ull; }

        for (int kc = 0; kc < C2; kc += KC) {
            __syncthreads();
            for (int idx = tid; idx < BB*KC; idx += NTHR) {
                int b = idx >> 7, kk = idx & (KC-1);
                sAct[b*ACT_STR + kk] = __ldcg(g_y + (size_t)b*C2 + kc + kk);
            }
            __syncthreads();

            const float* w0p = sWb + (2*bJ)*WB_STR + kc;
            const float* w1p = w0p + WB_STR;
            const int kb = bKs * 16;
            #pragma unroll
            for (int kk = 0; kk < 16; kk += 2) {
                ull w0 = ld64(w0p + kb + kk);
                ull w1 = ld64(w1p + kb + kk);
                #pragma unroll
                for (int i = 0; i < 4; ++i) {
                    ull a = ld64(sAct + (bB + 8*i)*ACT_STR + kb + kk);
                    ffma2(acc2[i][0], a, w0);
                    ffma2(acc2[i][1], a, w1);
                }
            }
        }
        {
            float part[4][2];
            #pragma unroll
            for (int i = 0; i < 4; ++i) {
                part[i][0] = hsum(acc2[i][0]);
                part[i][1] = hsum(acc2[i][1]);
            }
            if (bKs) {
                #pragma unroll
                for (int i = 0; i < 4; ++i) {
                    sRed[(((bKs-1)*32 + bSlot)*8) + i*2 + 0] = part[i][0];
                    sRed[(((bKs-1)*32 + bSlot)*8) + i*2 + 1] = part[i][1];
                }
            }
            __syncthreads();
            if (bKs == 0) {
                #pragma unroll
                for (int i = 0; i < 4; ++i) {
                    #pragma unroll
                    for (int j = 0; j < 2; ++j) {
                        float v = part[i][j];
                        #pragma unroll
                        for (int p = 0; p < 7; ++p)
                            v += sRed[((p*32 + bSlot)*8) + i*2 + j];
                        int jg = cta*8 + 2*bJ + j;
                        float u = v + __ldg(bbv + jg);
                        __stcg(&g_y2[(size_t)(bB + 8*i)*CC + jg], u);
                    }
                }
            }
        }
        gbar();

        // ================= Phase C: h = LN(y2)*gamma + beta + y2 =================
        {
            float s = 0.f, sq = 0.f;
            for (int i = tid; i < CC; i += NTHR) {
                float v = __ldcg(g_y2 + (size_t)myB*CC + i);
                s += v; sq += v*v;
            }
            #pragma unroll
            for (int o = 16; o; o >>= 1) {
                s  += __shfl_xor_sync(0xffffffffu, s,  o);
                sq += __shfl_xor_sync(0xffffffffu, sq, o);
            }
            if ((tid & 31) == 0) { sRed[tid >> 5] = s; sRed[8 + (tid >> 5)] = sq; }
            __syncthreads();
            float S = 0.f, Q = 0.f;
            #pragma unroll
            for (int w = 0; w < 8; ++w) { S += sRed[w]; Q += sRed[8 + w]; }
            float mu  = S * (1.0f / CC);
            float var = Q * (1.0f / CC) - mu * mu;
            float r   = rsqrtf(var + 1e-5f);
            int col = myQ * 256 + tid;
            float v  = __ldcg(g_y2 + (size_t)myB*CC + col);
            float hn = (v - mu) * r * __ldg(gamma + col) + __ldg(beta + col) + v;
            __stcg(g_h + (size_t)myB*CC + col, hn);
            out[(size_t)myB*TT*CC + (size_t)t*CC + col] = hn;
        }
        gbar();
    }
}

extern "C" void kernel_launch(void* const* d_in, const int* in_sizes, int n_in,
                              void* d_out, int out_size) {
    const float* x     = (const float*)d_in[0];
    const float* Wa    = (const float*)d_in[1];
    const float* ba    = (const float*)d_in[2];
    const float* Wb    = (const float*)d_in[3];
    const float* bbv   = (const float*)d_in[4];
    const float* gamma = (const float*)d_in[5];
    const float* beta  = (const float*)d_in[6];
    float* out = (float*)d_out;

    cudaFuncSetAttribute(rnn_kernel, cudaFuncAttributeMaxDynamicSharedMemorySize, SMEM_BYTES);
    rnn_kernel<<<NBLK, NTHR, SMEM_BYTES>>>(x, Wa, ba, Wb, bbv, gamma, beta, out);
}

// round 3
// speedup vs baseline: 1.9351x; 1.9351x over previous
#include <cuda_runtime.h>
#include <math.h>

typedef unsigned long long ull;

#define NBLK 128
#define NTHR 512
#define BB   32
#define CC   1024
#define C2   2048
#define TT   1024
#define KC   128
#define WA_STR 2052
#define WB_STR 2052
#define ACT_STR 132

// SMEM (floats): sWa 16*2052, sWb 8*2052, sAct 32*132, sRed 3840
#define SMEM_FLOATS (16*WA_STR + 8*WB_STR + 32*ACT_STR + 3840)
#define SMEM_BYTES  (SMEM_FLOATS * 4)

__device__ float g_h [BB*CC];
__device__ float g_y [BB*C2];
__device__ float g_y2[BB*CC];
__device__ unsigned g_cnt;
__device__ volatile unsigned g_gen;

__device__ __forceinline__ void ffma2(ull& d, ull a, ull b) {
    asm volatile("fma.rn.f32x2 %0, %1, %2, %0;" : "+l"(d) : "l"(a), "l"(b));
}
__device__ __forceinline__ float hsum(ull a) {
    return __uint_as_float((unsigned)a) + __uint_as_float((unsigned)(a >> 32));
}
__device__ __forceinline__ float geluf(float u) {
    return 0.5f * u * (1.0f + erff(u * 0.70710678118654752440f));
}

// Grid-wide barrier: counter + generation. Replay-safe (cnt returns to 0,
// gen monotonic). All 128 CTAs are co-resident (1 CTA/SM via SMEM).
__device__ __forceinline__ void gbar() {
    __syncthreads();
    if (threadIdx.x == 0) {
        __threadfence();
        unsigned gen = g_gen;
        if (atomicAdd(&g_cnt, 1u) == NBLK - 1) {
            atomicExch(&g_cnt, 0u);
            __threadfence();
            g_gen = gen + 1u;
        } else {
            while (g_gen == gen) {}
        }
        __threadfence();
    }
    __syncthreads();
}

// Load one float4 of the phase-A activation matrix [h | x_t] chunk.
__device__ __forceinline__ float4 ldsrcA(const float* __restrict__ x, int t, int kc, int fi) {
    int b = fi >> 5, kk = (fi & 31) << 2;
    const float* p;
    if (kc < CC) p = g_h + (size_t)b*CC + kc + kk;
    else         p = x + (size_t)b*TT*CC + (size_t)t*CC + (kc - CC) + kk;
    return __ldcg((const float4*)p);
}
__device__ __forceinline__ float4 ldsrcB(int kc, int fi) {
    int b = fi >> 5, kk = (fi & 31) << 2;
    return __ldcg((const float4*)(g_y + (size_t)b*C2 + kc + kk));
}

__global__ void __launch_bounds__(NTHR, 1)
rnn_kernel(const float* __restrict__ x,   const float* __restrict__ Wa,
           const float* __restrict__ ba,  const float* __restrict__ Wb,
           const float* __restrict__ bbv, const float* __restrict__ gamma,
           const float* __restrict__ beta, float* __restrict__ out)
{
    extern __shared__ float sm[];
    float* sWa  = sm;
    float* sWb  = sm + 16*WA_STR;
    float* sAct = sWb + 8*WB_STR;
    float* sRed = sAct + 32*ACT_STR;

    const int tid = threadIdx.x;
    const int cta = blockIdx.x;

    for (int idx = tid; idx < 16*C2; idx += NTHR) {
        int r = idx >> 11, k = idx & (C2-1);
        sWa[r*WA_STR + k] = Wa[(size_t)(cta*16 + r)*C2 + k];
    }
    for (int idx = tid; idx < 8*C2; idx += NTHR) {
        int r = idx >> 11, k = idx & (C2-1);
        sWb[r*WB_STR + k] = Wb[(size_t)(cta*8 + r)*C2 + k];
    }
    {
        int idx = cta*NTHR + tid;
        if (idx < BB*CC) g_h[idx] = 0.0f;
    }
    gbar();

    // Phase A: 64 slots (8 b x 8 j-pairs), 8-way K split (ks = tid>>6, const per warp)
    const int aSlot = tid & 63, aKs = tid >> 6;
    const int aB = aSlot & 7, aJ = aSlot >> 3;
    const int akb = aKs * 16;
    // Phase B: 32 slots (8 b x 4 j-pairs), 16-way K split
    const int bSlot = tid & 31, bKs = tid >> 5;
    const int bB = bSlot & 7, bJ = bSlot >> 3;
    const int bkb = bKs * 8;
    // Phase C
    const int myB = cta >> 2, myQ = cta & 3;

    const int fi0 = 2*tid, fi1 = 2*tid + 1;
    const int sa0 = (fi0 >> 5)*ACT_STR + ((fi0 & 31) << 2);
    const int sa1 = (fi1 >> 5)*ACT_STR + ((fi1 & 31) << 2);

    for (int t = 0; t < TT; ++t) {
        // ============ Phase A: y = gelu([h, x_t] @ Wa^T + ba) ============
        ull acc[4][2];
        #pragma unroll
        for (int i = 0; i < 4; ++i) { acc[i][0] = 0ull; acc[i][1] = 0ull; }

        float4 p0 = ldsrcA(x, t, 0, fi0);
        float4 p1 = ldsrcA(x, t, 0, fi1);

        for (int kc = 0; kc < C2; kc += KC) {
            __syncthreads();
            *(float4*)(sAct + sa0) = p0;
            *(float4*)(sAct + sa1) = p1;
            __syncthreads();
            if (kc + KC < C2) {
                p0 = ldsrcA(x, t, kc + KC, fi0);
                p1 = ldsrcA(x, t, kc + KC, fi1);
            }
            const float* w0p = sWa + (2*aJ)*WA_STR + kc + akb;
            const float* w1p = w0p + WA_STR;
            #pragma unroll
            for (int q = 0; q < 4; ++q) {
                ulonglong2 w0 = *(const ulonglong2*)(w0p + q*4);
                ulonglong2 w1 = *(const ulonglong2*)(w1p + q*4);
                #pragma unroll
                for (int i = 0; i < 4; ++i) {
                    ulonglong2 a = *(const ulonglong2*)(sAct + (aB + 8*i)*ACT_STR + akb + q*4);
                    ffma2(acc[i][0], a.x, w0.x);
                    ffma2(acc[i][0], a.y, w0.y);
                    ffma2(acc[i][1], a.x, w1.x);
                    ffma2(acc[i][1], a.y, w1.y);
                }
            }
        }
        {
            float part[4][2];
            #pragma unroll
            for (int i = 0; i < 4; ++i) {
                part[i][0] = hsum(acc[i][0]);
                part[i][1] = hsum(acc[i][1]);
            }
            if (aKs) {
                #pragma unroll
                for (int i = 0; i < 4; ++i) {
                    sRed[(((aKs-1)*64 + aSlot)*8) + i*2 + 0] = part[i][0];
                    sRed[(((aKs-1)*64 + aSlot)*8) + i*2 + 1] = part[i][1];
                }
            }
            __syncthreads();
            if (aKs == 0) {
                #pragma unroll
                for (int i = 0; i < 4; ++i) {
                    #pragma unroll
                    for (int j = 0; j < 2; ++j) {
                        float v = part[i][j];
                        #pragma unroll
                        for (int p = 0; p < 7; ++p)
                            v += sRed[((p*64 + aSlot)*8) + i*2 + j];
                        int jg = cta*16 + 2*aJ + j;
                        float u = v + __ldg(ba + jg);
                        __stcg(&g_y[(size_t)(aB + 8*i)*C2 + jg], geluf(u));
                    }
                }
            }
        }
        gbar();

        // ============ Phase B: y2 = y @ Wb^T + bb ============
        ull acc2[4][2];
        #pragma unroll
        for (int i = 0; i < 4; ++i) { acc2[i][0] = 0ull; acc2[i][1] = 0ull; }

        p0 = ldsrcB(0, fi0);
        p1 = ldsrcB(0, fi1);

        for (int kc = 0; kc < C2; kc += KC) {
            __syncthreads();
            *(float4*)(sAct + sa0) = p0;
            *(float4*)(sAct + sa1) = p1;
            __syncthreads();
            if (kc + KC < C2) {
                p0 = ldsrcB(kc + KC, fi0);
                p1 = ldsrcB(kc + KC, fi1);
            }
            const float* w0p = sWb + (2*bJ)*WB_STR + kc + bkb;
            const float* w1p = w0p + WB_STR;
            #pragma unroll
            for (int q = 0; q < 2; ++q) {
                ulonglong2 w0 = *(const ulonglong2*)(w0p + q*4);
                ulonglong2 w1 = *(const ulonglong2*)(w1p + q*4);
                #pragma unroll
                for (int i = 0; i < 4; ++i) {
                    ulonglong2 a = *(const ulonglong2*)(sAct + (bB + 8*i)*ACT_STR + bkb + q*4);
                    ffma2(acc2[i][0], a.x, w0.x);
                    ffma2(acc2[i][0], a.y, w0.y);
                    ffma2(acc2[i][1], a.x, w1.x);
                    ffma2(acc2[i][1], a.y, w1.y);
                }
            }
        }
        {
            float part[4][2];
            #pragma unroll
            for (int i = 0; i < 4; ++i) {
                part[i][0] = hsum(acc2[i][0]);
                part[i][1] = hsum(acc2[i][1]);
            }
            if (bKs) {
                #pragma unroll
                for (int i = 0; i < 4; ++i) {
                    sRed[(((bKs-1)*32 + bSlot)*8) + i*2 + 0] = part[i][0];
                    sRed[(((bKs-1)*32 + bSlot)*8) + i*2 + 1] = part[i][1];
                }
            }
            __syncthreads();
            if (bKs == 0) {
                #pragma unroll
                for (int i = 0; i < 4; ++i) {
                    #pragma unroll
                    for (int j = 0; j < 2; ++j) {
                        float v = part[i][j];
                        #pragma unroll
                        for (int p = 0; p < 15; ++p)
                            v += sRed[((p*32 + bSlot)*8) + i*2 + j];
                        int jg = cta*8 + 2*bJ + j;
                        float u = v + __ldg(bbv + jg);
                        __stcg(&g_y2[(size_t)(bB + 8*i)*CC + jg], u);
                    }
                }
            }
        }
        gbar();

        // ============ Phase C: h = LN(y2)*gamma + beta + y2 ============
        {
            float s = 0.f, sq = 0.f;
            #pragma unroll
            for (int i = tid; i < CC; i += NTHR) {
                float v = __ldcg(g_y2 + (size_t)myB*CC + i);
                s += v; sq += v*v;
            }
            #pragma unroll
            for (int o = 16; o; o >>= 1) {
                s  += __shfl_xor_sync(0xffffffffu, s,  o);
                sq += __shfl_xor_sync(0xffffffffu, sq, o);
            }
            if ((tid & 31) == 0) { sRed[tid >> 5] = s; sRed[16 + (tid >> 5)] = sq; }
            __syncthreads();
            if (tid < 256) {
                float S = 0.f, Q = 0.f;
                #pragma unroll
                for (int w = 0; w < 16; ++w) { S += sRed[w]; Q += sRed[16 + w]; }
                float mu  = S * (1.0f / CC);
                float var = Q * (1.0f / CC) - mu * mu;
                float r   = rsqrtf(var + 1e-5f);
                int col = myQ * 256 + tid;
                float v  = __ldcg(g_y2 + (size_t)myB*CC + col);
                float hn = (v - mu) * r * __ldg(gamma + col) + __ldg(beta + col) + v;
                __stcg(g_h + (size_t)myB*CC + col, hn);
                out[(size_t)myB*TT*CC + (size_t)t*CC + col] = hn;
            }
        }
        gbar();
    }
}

extern "C" void kernel_launch(void* const* d_in, const int* in_sizes, int n_in,
                              void* d_out, int out_size) {
    const float* x     = (const float*)d_in[0];
    const float* Wa    = (const float*)d_in[1];
    const float* ba    = (const float*)d_in[2];
    const float* Wb    = (const float*)d_in[3];
    const float* bbv   = (const float*)d_in[4];
    const float* gamma = (const float*)d_in[5];
    const float* beta  = (const float*)d_in[6];
    float* out = (float*)d_out;

    cudaFuncSetAttribute(rnn_kernel, cudaFuncAttributeMaxDynamicSharedMemorySize, SMEM_BYTES);
    rnn_kernel<<<NBLK, NTHR, SMEM_BYTES>>>(x, Wa, ba, Wb, bbv, gamma, beta, out);
}

// round 7
// speedup vs baseline: 3.2520x; 1.6805x over previous
#include <cuda_runtime.h>
#include <cuda_bf16.h>
#include <math.h>
#include <stdint.h>

typedef uint32_t u32;

#define NBLK 128
#define NTHR 512
#define BB   32
#define CC   1024
#define C2   2048
#define TT   1024
#define KC   128
#define WS   2056   // weight row stride (bf16 elems), 4112B: conflict-free LDSM
#define AS   136    // act row stride (bf16 elems), 272B: conflict-free LDSM

// SMEM layout (bf16-element offsets, then float sRed)
#define OFF_WAHI  0
#define OFF_WALO  (16*WS)
#define OFF_WBHI  (32*WS)
#define OFF_WBLO  (40*WS)
#define OFF_ACTHI (48*WS)
#define OFF_ACTLO (48*WS + 32*AS)
#define OFF_END   (48*WS + 64*AS)
#define SRED_FLOATS 2560
#define SMEM_BYTES (OFF_END*2 + SRED_FLOATS*4)   // 225,024 B

__device__ __nv_bfloat16 g_x_hi[33554432];
__device__ __nv_bfloat16 g_x_lo[33554432];
__device__ __nv_bfloat16 g_h_hi[BB*CC];
__device__ __nv_bfloat16 g_h_lo[BB*CC];
__device__ __nv_bfloat16 g_y_hi[BB*C2];
__device__ __nv_bfloat16 g_y_lo[BB*C2];
__device__ float g_y2[BB*CC];
__device__ unsigned g_cnt;
__device__ volatile unsigned g_gen;

__device__ __forceinline__ float geluf(float u) {
    return 0.5f * u * (1.0f + erff(u * 0.70710678118654752440f));
}

__device__ __forceinline__ void gbar() {
    __syncthreads();
    if (threadIdx.x == 0) {
        __threadfence();
        unsigned gen = g_gen;
        if (atomicAdd(&g_cnt, 1u) == NBLK - 1) {
            atomicExch(&g_cnt, 0u);
            __threadfence();
            g_gen = gen + 1u;
        } else {
            while (g_gen == gen) {}
        }
        __threadfence();
    }
    __syncthreads();
}

__device__ __forceinline__ void ldsm4(u32 (&r)[4], u32 addr) {
    asm volatile("ldmatrix.sync.aligned.m8n8.x4.shared.b16 {%0,%1,%2,%3}, [%4];"
        : "=r"(r[0]), "=r"(r[1]), "=r"(r[2]), "=r"(r[3]) : "r"(addr));
}
__device__ __forceinline__ void ldsm2(u32 (&r)[2], u32 addr) {
    asm volatile("ldmatrix.sync.aligned.m8n8.x2.shared.b16 {%0,%1}, [%2];"
        : "=r"(r[0]), "=r"(r[1]) : "r"(addr));
}
__device__ __forceinline__ void mma16816(float (&c)[4], const u32 (&a)[4], const u32 (&b)[2]) {
    asm volatile("mma.sync.aligned.m16n8k16.row.col.f32.bf16.bf16.f32 "
        "{%0,%1,%2,%3}, {%4,%5,%6,%7}, {%8,%9}, {%0,%1,%2,%3};"
        : "+f"(c[0]), "+f"(c[1]), "+f"(c[2]), "+f"(c[3])
        : "r"(a[0]), "r"(a[1]), "r"(a[2]), "r"(a[3]), "r"(b[0]), "r"(b[1]));
}

// split v -> hi (bf16) + lo (bf16 of remainder)
__device__ __forceinline__ void split2(float v, __nv_bfloat16& h, __nv_bfloat16& l) {
    h = __float2bfloat16_rn(v);
    l = __float2bfloat16_rn(v - __bfloat162float(h));
}

__global__ void __launch_bounds__(NTHR, 1)
rnn_kernel(const float* __restrict__ x,   const float* __restrict__ Wa,
           const float* __restrict__ ba,  const float* __restrict__ Wb,
           const float* __restrict__ bbv, const float* __restrict__ gamma,
           const float* __restrict__ beta, float* __restrict__ out)
{
    extern __shared__ __nv_bfloat16 smb[];
    __nv_bfloat16* sWaHi = smb + OFF_WAHI;
    __nv_bfloat16* sWaLo = smb + OFF_WALO;
    __nv_bfloat16* sWbHi = smb + OFF_WBHI;
    __nv_bfloat16* sWbLo = smb + OFF_WBLO;
    __nv_bfloat16* sActHi = smb + OFF_ACTHI;
    __nv_bfloat16* sActLo = smb + OFF_ACTLO;
    float* sRed = (float*)(smb + OFF_END);

    const int tid = threadIdx.x;
    const int cta = blockIdx.x;
    const int lane = tid & 31, wid = tid >> 5;

    // ---- one-time: weights -> smem bf16 hi/lo planes ----
    for (int idx = tid; idx < 16*C2; idx += NTHR) {
        int r = idx >> 11, k = idx & (C2-1);
        float v = Wa[(size_t)(cta*16 + r)*C2 + k];
        split2(v, sWaHi[r*WS + k], sWaLo[r*WS + k]);
    }
    for (int idx = tid; idx < 8*C2; idx += NTHR) {
        int r = idx >> 11, k = idx & (C2-1);
        float v = Wb[(size_t)(cta*8 + r)*C2 + k];
        split2(v, sWbHi[r*WS + k], sWbLo[r*WS + k]);
    }
    // ---- one-time: x -> bf16 hi/lo global planes ----
    {
        int g = cta*NTHR + tid;
        const float4* x4 = (const float4*)x;
        uint2* xh = (uint2*)g_x_hi;
        uint2* xl = (uint2*)g_x_lo;
        for (int i = 0; i < 128; ++i) {
            int idx = g + (i << 16);
            float4 v = x4[idx];
            __nv_bfloat16 h0,h1,h2,h3,l0,l1,l2,l3;
            split2(v.x,h0,l0); split2(v.y,h1,l1); split2(v.z,h2,l2); split2(v.w,h3,l3);
            __nv_bfloat162 ph0 = {h0,h1}, ph1 = {h2,h3}, pl0 = {l0,l1}, pl1 = {l2,l3};
            uint2 uh, ul;
            uh.x = *(u32*)&ph0; uh.y = *(u32*)&ph1;
            ul.x = *(u32*)&pl0; ul.y = *(u32*)&pl1;
            xh[idx] = uh; xl[idx] = ul;
        }
    }
    // h0 = 0
    {
        int idx = cta*NTHR + tid;
        if (idx < BB*CC) {
            g_h_hi[idx] = __float2bfloat16_rn(0.f);
            g_h_lo[idx] = __float2bfloat16_rn(0.f);
        }
    }
    gbar();

    // ---- warp roles ----
    // Phase A: D[16j x 32b] = Wa_slice @ ActT ; warp = (nt, kspA): nt = wid>>2 (n-tile of 8 b), kspA = wid&3
    const int kspA = wid & 3, nt = wid >> 2;
    // Phase B: D[32b x 8j] = Act @ WbT ; warp = (mt, kspB): mt = wid&1, kspB = wid>>1
    const int mtB = wid & 1, kspB = wid >> 1;
    // Phase C
    const int myB = cta >> 2, myQ = cta & 3;

    // ldmatrix smem byte addresses (u32 shared-space)
    const u32 smemBase = (u32)__cvta_generic_to_shared(smb);
    const u32 waHiB = smemBase + OFF_WAHI*2, waLoB = smemBase + OFF_WALO*2;
    const u32 wbHiB = smemBase + OFF_WBHI*2, wbLoB = smemBase + OFF_WBLO*2;
    const u32 acHiB = smemBase + OFF_ACTHI*2, acLoB = smemBase + OFF_ACTLO*2;

    // A-frag lane addressing (16x16 from row-major rows, k-halves)
    const int aRow = lane & 15, aKh = (lane >> 4) * 8;
    // B-frag lane addressing (8 rows, k-halves), lanes 0-15 meaningful
    const int bRow = lane & 7, bKh = ((lane >> 3) & 1) * 8;

    // phase A frag bases (byte offsets added per kstep)
    const u32 aA_hi = waHiB + (aRow*WS + aKh)*2;     // + kb*2
    const u32 aA_lo = waLoB + (aRow*WS + aKh)*2;
    const u32 aB_hi = acHiB + ((nt*8 + bRow)*AS + bKh)*2;  // + kl*2
    const u32 aB_lo = acLoB + ((nt*8 + bRow)*AS + bKh)*2;
    // phase B frag bases
    const u32 bA_hi = acHiB + ((mtB*16 + aRow)*AS + aKh)*2; // + kl*2
    const u32 bA_lo = acLoB + ((mtB*16 + aRow)*AS + aKh)*2;
    const u32 bB_hi = wbHiB + (bRow*WS + bKh)*2;            // + kb*2
    const u32 bB_lo = wbLoB + (bRow*WS + bKh)*2;

    // staging mapping: thread -> (row = tid>>4, kk = (tid&15)*8)
    const int srow = tid >> 4, skk = (tid & 15) << 3;
    __nv_bfloat16* stHi = sActHi + srow*AS + skk;
    __nv_bfloat16* stLo = sActLo + srow*AS + skk;

    for (int t = 0; t < TT; ++t) {
        // ================= Phase A =================
        float c[4] = {0.f, 0.f, 0.f, 0.f};
        uint4 h4, l4;
        {   // prefetch chunk 0 (h region)
            const __nv_bfloat16* ph = g_h_hi + srow*CC + skk;
            const __nv_bfloat16* pl = g_h_lo + srow*CC + skk;
            h4 = __ldcg((const uint4*)ph);
            l4 = __ldcg((const uint4*)pl);
        }
        for (int ch = 0; ch < 16; ++ch) {
            const int kc = ch * KC;
            __syncthreads();
            *(uint4*)stHi = h4;
            *(uint4*)stLo = l4;
            __syncthreads();
            if (ch < 15) {
                int kn = kc + KC;
                if (kn < CC) {
                    h4 = __ldcg((const uint4*)(g_h_hi + srow*CC + kn + skk));
                    l4 = __ldcg((const uint4*)(g_h_lo + srow*CC + kn + skk));
                } else {
                    size_t o = ((size_t)srow << 20) + ((size_t)t << 10) + (kn - CC) + skk;
                    h4 = __ldcg((const uint4*)(g_x_hi + o));
                    l4 = __ldcg((const uint4*)(g_x_lo + o));
                }
            }
            #pragma unroll
            for (int u = 0; u < 2; ++u) {
                const int l = 2*kspA + u;
                const int kb = kc + 16*l;   // global k (weights)
                const int kl = 16*l;        // local k (act)
                u32 Ah[4], Al[4], Bh[2], Bl[2];
                ldsm4(Ah, aA_hi + kb*2);
                ldsm4(Al, aA_lo + kb*2);
                ldsm2(Bh, aB_hi + kl*2);
                ldsm2(Bl, aB_lo + kl*2);
                mma16816(c, Ah, Bh);
                mma16816(c, Ah, Bl);
                mma16816(c, Al, Bh);
            }
        }
        {   // partials -> sRed[kspA][16j][32b] (row stride 34)
            const int r0 = lane >> 2, cb = nt*8 + 2*(lane & 3);
            *(float2*)(sRed + (kspA*16 + r0    )*34 + cb) = make_float2(c[0], c[1]);
            *(float2*)(sRed + (kspA*16 + r0 + 8)*34 + cb) = make_float2(c[2], c[3]);
            __syncthreads();
            // reduce + gelu + emit y hi/lo planes: b = tid>>4, j = tid&15
            const int b = tid >> 4, j = tid & 15;
            float v = sRed[j*34 + b] + sRed[(16 + j)*34 + b]
                    + sRed[(32 + j)*34 + b] + sRed[(48 + j)*34 + b];
            const int jg = cta*16 + j;
            float y = geluf(v + __ldg(ba + jg));
            __nv_bfloat16 hh, ll;
            split2(y, hh, ll);
            g_y_hi[(size_t)b*C2 + jg] = hh;
            g_y_lo[(size_t)b*C2 + jg] = ll;
        }
        gbar();

        // ================= Phase B =================
        float c2[4] = {0.f, 0.f, 0.f, 0.f};
        h4 = __ldcg((const uint4*)(g_y_hi + srow*C2 + skk));
        l4 = __ldcg((const uint4*)(g_y_lo + srow*C2 + skk));
        for (int ch = 0; ch < 16; ++ch) {
            const int kc = ch * KC;
            __syncthreads();
            *(uint4*)stHi = h4;
            *(uint4*)stLo = l4;
            __syncthreads();
            if (ch < 15) {
                int kn = kc + KC;
                h4 = __ldcg((const uint4*)(g_y_hi + srow*C2 + kn + skk));
                l4 = __ldcg((const uint4*)(g_y_lo + srow*C2 + kn + skk));
            }
            {
                const int l = kspB;
                const int kb = kc + 16*l;
                const int kl = 16*l;
                u32 Ah[4], Al[4], Bh[2], Bl[2];
                ldsm4(Ah, bA_hi + kl*2);
                ldsm4(Al, bA_lo + kl*2);
                ldsm2(Bh, bB_hi + kb*2);
                ldsm2(Bl, bB_lo + kb*2);
                mma16816(c2, Ah, Bh);
                mma16816(c2, Ah, Bl);
                mma16816(c2, Al, Bh);
            }
        }
        {   // partials -> sRed[kspB][32b][8j] (row stride 10)
            const int r0 = mtB*16 + (lane >> 2), cb = 2*(lane & 3);
            *(float2*)(sRed + (kspB*32 + r0    )*10 + cb) = make_float2(c2[0], c2[1]);
            *(float2*)(sRed + (kspB*32 + r0 + 8)*10 + cb) = make_float2(c2[2], c2[3]);
            __syncthreads();
            if (tid < 256) {
                const int b = tid >> 3, j = tid & 7;
                float v = 0.f;
                #pragma unroll
                for (int p = 0; p < 8; ++p) v += sRed[(p*32 + b)*10 + j];
                const int jg = cta*8 + j;
                v += __ldg(bbv + jg);
                __stcg(&g_y2[(size_t)b*CC + jg], v);
            }
        }
        gbar();

        // ================= Phase C: h = LN(y2)+y2 =================
        {
            float s = 0.f, sq = 0.f;
            #pragma unroll
            for (int i = tid; i < CC; i += NTHR) {
                float v = __ldcg(g_y2 + (size_t)myB*CC + i);
                s += v; sq += v*v;
            }
            #pragma unroll
            for (int o = 16; o; o >>= 1) {
                s  += __shfl_xor_sync(0xffffffffu, s,  o);
                sq += __shfl_xor_sync(0xffffffffu, sq, o);
            }
            if (lane == 0) { sRed[wid] = s; sRed[16 + wid] = sq; }
            __syncthreads();
            if (tid < 256) {
                float S = 0.f, Q = 0.f;
                #pragma unroll
                for (int w = 0; w < 16; ++w) { S += sRed[w]; Q += sRed[16 + w]; }
                float mu  = S * (1.0f / CC);
                float var = Q * (1.0f / CC) - mu * mu;
                float r   = rsqrtf(var + 1e-5f);
                int col = myQ * 256 + tid;
                float v  = __ldcg(g_y2 + (size_t)myB*CC + col);
                float hn = (v - mu) * r * __ldg(gamma + col) + __ldg(beta + col) + v;
                out[(size_t)myB*TT*CC + (size_t)t*CC + col] = hn;
                __nv_bfloat16 hh, ll;
                split2(hn, hh, ll);
                g_h_hi[(size_t)myB*CC + col] = hh;
                g_h_lo[(size_t)myB*CC + col] = ll;
            }
        }
        gbar();
    }
}

extern "C" void kernel_launch(void* const* d_in, const int* in_sizes, int n_in,
                              void* d_out, int out_size) {
    const float* x     = (const float*)d_in[0];
    const float* Wa    = (const float*)d_in[1];
    const float* ba    = (const float*)d_in[2];
    const float* Wb    = (const float*)d_in[3];
    const float* bbv   = (const float*)d_in[4];
    const float* gamma = (const float*)d_in[5];
    const float* beta  = (const float*)d_in[6];
    float* out = (float*)d_out;

    cudaFuncSetAttribute(rnn_kernel, cudaFuncAttributeMaxDynamicSharedMemorySize, SMEM_BYTES);
    rnn_kernel<<<NBLK, NTHR, SMEM_BYTES>>>(x, Wa, ba, Wb, bbv, gamma, beta, out);
}